// round 8
// baseline (speedup 1.0000x reference)
#include <cuda_runtime.h>
#include <cuda_bf16.h>
#include <math.h>
#include <stdint.h>

// ----------------------------------------------------------------------------
// DecoderLSTMWithAttention — R8:
//   - chain restructured: gate-grouped N ownership (block owns 4 cols x 4 gates,
//     full K) -> no split-K partials, c-state in smem, ONE grid barrier/step,
//     pack-free f32x2 row-pair micro-kernel (B duplicated in smem)
//   - logits: k-chunk 32, 3-stage cp.async pipeline (96KB dynamic smem, occ 2)
//   - rest as R7 (fused prep, gpre occ-2, tile-max argmax w/ exact recheck)
// ----------------------------------------------------------------------------

#define Bb 128
#define Hh 512
#define Tt 27
#define Vv 30000
#define NBLK 128
#define VPAD 30208
#define NTILES 235
#define TMSTRIDE 236

// scratch (device globals: no allocations allowed)
__device__ float g_v0[512];
__device__ float g_v1[512];
__device__ float g_q[512];
__device__ float g_ctx[128 * 512];
__device__ float g_Gpre[27u * 128u * 2048u];
__device__ float g_H2[27u * 128u * 512u];
__device__ unsigned g_bar_cnt;
__device__ unsigned g_bar_gen;
__device__ float g_tilemax[3456u * TMSTRIDE];
__device__ __nv_bfloat16 g_Ahi[3456u * 512u];
__device__ __nv_bfloat16 g_Alo[3456u * 512u];
__device__ __nv_bfloat16 g_Whi[(unsigned)VPAD * 512u];
__device__ __nv_bfloat16 g_Wlo[(unsigned)VPAD * 512u];

// ---------------- packed fp32x2 helpers ----------------
__device__ __forceinline__ unsigned long long pack2(float x) {
    unsigned long long r;
    asm("mov.b64 %0, {%1, %1};" : "=l"(r) : "f"(x));
    return r;
}
__device__ __forceinline__ void ffma2(unsigned long long& d, unsigned long long a, unsigned long long b) {
    asm("fma.rn.f32x2 %0, %1, %2, %0;" : "+l"(d) : "l"(a), "l"(b));
}
__device__ __forceinline__ float2 unpack2(unsigned long long v) {
    float lo, hi;
    asm("mov.b64 {%0, %1}, %2;" : "=f"(lo), "=f"(hi) : "l"(v));
    return make_float2(lo, hi);
}

// ---------------- ptx helpers ----------------------------------------------------
__device__ __forceinline__ uint32_t smem_u32(const void* p) {
    uint32_t a;
    asm("{ .reg .u64 t; cvta.to.shared.u64 t, %1; cvt.u32.u64 %0, t; }" : "=r"(a) : "l"(p));
    return a;
}
__device__ __forceinline__ void cp16(uint32_t dst, const void* src) {
    asm volatile("cp.async.cg.shared.global [%0], [%1], 16;" :: "r"(dst), "l"(src));
}
#define CP_COMMIT() asm volatile("cp.async.commit_group;" ::: "memory")
#define CP_WAIT1()  asm volatile("cp.async.wait_group 1;" ::: "memory")
__device__ __forceinline__ void ldm_x4(uint32_t* r, uint32_t addr) {
    asm volatile("ldmatrix.sync.aligned.m8n8.x4.shared.b16 {%0,%1,%2,%3}, [%4];"
        : "=r"(r[0]), "=r"(r[1]), "=r"(r[2]), "=r"(r[3]) : "r"(addr));
}
__device__ __forceinline__ void mma_bf16(float* d, const uint32_t* a, const uint32_t* b) {
    asm volatile("mma.sync.aligned.m16n8k16.row.col.f32.bf16.bf16.f32 "
        "{%0,%1,%2,%3}, {%4,%5,%6,%7}, {%8,%9}, {%0,%1,%2,%3};"
        : "+f"(d[0]), "+f"(d[1]), "+f"(d[2]), "+f"(d[3])
        : "r"(a[0]), "r"(a[1]), "r"(a[2]), "r"(a[3]), "r"(b[0]), "r"(b[1]));
}
__device__ __forceinline__ unsigned fenc(float x) {
    int i = __float_as_int(x);
    return (i >= 0) ? ((unsigned)i | 0x80000000u) : ~(unsigned)i;
}
__device__ __forceinline__ float fdec(unsigned e) {
    int i = (e & 0x80000000u) ? (int)(e & 0x7fffffffu) : ~(int)e;
    return __int_as_float(i);
}

// ---------------- software grid barrier (tight spin, launch-relative) ----------
__device__ __forceinline__ void gsync(unsigned target) {
    __syncthreads();
    if (threadIdx.x == 0) {
        __threadfence();
        unsigned prev = atomicAdd(&g_bar_cnt, 1u);
        if (prev == NBLK - 1) {
            g_bar_cnt = 0;
            __threadfence();
            *(volatile unsigned*)&g_bar_gen = target;
        } else {
            volatile unsigned* vg = (volatile unsigned*)&g_bar_gen;
            while ((int)(*vg - target) < 0) {}
        }
        __threadfence();
    }
    __syncthreads();
}

// ---------------- FFMA2 GEMM micro-kernel (gpre) --------------------------------
__device__ __forceinline__ void tile_fma(const float* As, const float* Bs, int tr, int tc,
                                         unsigned long long acc[8][4]) {
    #pragma unroll
    for (int kk = 0; kk < 16; kk++) {
        float4 a0 = *(const float4*)(As + kk * 128 + tr * 4);
        float4 a1 = *(const float4*)(As + kk * 128 + 64 + tr * 4);
        ulonglong2 b0 = *(const ulonglong2*)(Bs + kk * 128 + tc * 4);
        ulonglong2 b1 = *(const ulonglong2*)(Bs + kk * 128 + 64 + tc * 4);
        unsigned long long pb0 = b0.x, pb1 = b0.y, pb2 = b1.x, pb3 = b1.y;
        float av[8] = {a0.x, a0.y, a0.z, a0.w, a1.x, a1.y, a1.z, a1.w};
        #pragma unroll
        for (int i = 0; i < 8; i++) {
            unsigned long long pa = pack2(av[i]);
            ffma2(acc[i][0], pa, pb0);
            ffma2(acc[i][1], pa, pb1);
            ffma2(acc[i][2], pa, pb2);
            ffma2(acc[i][3], pa, pb3);
        }
    }
}
__device__ __forceinline__ void stT(float* S, int r, int lc, float4 v) {
    float* d = S + r;
    d[(lc + 0) * 128] = v.x;
    d[(lc + 1) * 128] = v.y;
    d[(lc + 2) * 128] = v.z;
    d[(lc + 3) * 128] = v.w;
}

// ---------------- fp32 -> (hi, lo) bf16 split (W_out) ---------------------------
__global__ void split_kernel(const float* __restrict__ src, __nv_bfloat16* __restrict__ hi,
                             __nv_bfloat16* __restrict__ lo, int n_src) {
    int i0 = (blockIdx.x * 256 + threadIdx.x) * 4;
    #pragma unroll
    for (int u = 0; u < 4; u++) {
        int i = i0 + u;
        float x = (i < n_src) ? src[i] : 0.f;
        __nv_bfloat16 h = __float2bfloat16_rn(x);
        __nv_bfloat16 l = __float2bfloat16_rn(x - __bfloat162float(h));
        hi[i] = h;
        lo[i] = l;
    }
}

// ---------------- fused prep: matvec fold -> attention (128 blocks) -------------
__global__ void __launch_bounds__(256) fused_prep(
    const float* __restrict__ w_att, const float* __restrict__ W4,
    const float* __restrict__ W3, const float* __restrict__ W2,
    const float* __restrict__ W1, const float* __restrict__ enc) {
    __shared__ float S[1024];
    int tid = threadIdx.x, bid = blockIdx.x;
    unsigned gen0 = *(volatile unsigned*)&g_bar_gen;

    const float* Ws[4] = {W4, W3, W2, W1};
    #pragma unroll 1
    for (int p = 0; p < 4; p++) {
        const float* W = Ws[p];
        int stride = (p == 3) ? 1024 : 512;
        const float* vin = (p == 0) ? w_att : ((p == 2) ? g_v1 : g_v0);
        float* vout = (p == 0) ? g_v0 : ((p == 1) ? g_v1 : ((p == 2) ? g_v0 : g_q));
        int k = bid * 4 + (tid & 3);
        int s = tid >> 2;
        float a = 0.f;
        #pragma unroll
        for (int u = 0; u < 8; u++) {
            int j = s * 8 + u;
            a += __ldcg(vin + j) * W[(size_t)j * stride + k];
        }
        S[tid] = a;
        __syncthreads();
        if (tid < 4) {
            float acc = 0.f;
            for (int s2 = 0; s2 < 64; s2++) acc += S[tid + 4 * s2];
            vout[bid * 4 + tid] = acc;
        }
        gsync(gen0 + 1 + p);
    }

    {
        float* sq = &S[0];
        float* sc = &S[512];
        int b = bid;
        sq[tid] = __ldcg(g_q + tid);
        sq[tid + 256] = __ldcg(g_q + tid + 256);
        __syncthreads();
        int w = tid >> 5, lane = tid & 31;
        for (int s = w; s < 80; s += 8) {
            const float* e = enc + ((size_t)b * 80 + s) * 512;
            float acc = 0.f;
            for (int k = lane; k < 512; k += 32) acc += e[k] * sq[k];
            #pragma unroll
            for (int o = 16; o; o >>= 1) acc += __shfl_xor_sync(0xffffffffu, acc, o);
            if (lane == 0) sc[s] = acc;
        }
        __syncthreads();
        if (tid < 32) {
            float m = -1e30f;
            for (int s = tid; s < 80; s += 32) m = fmaxf(m, sc[s]);
            #pragma unroll
            for (int o = 16; o; o >>= 1) m = fmaxf(m, __shfl_xor_sync(0xffffffffu, m, o));
            float sum = 0.f;
            for (int s = tid; s < 80; s += 32) { float e = expf(sc[s] - m); sc[s] = e; sum += e; }
            #pragma unroll
            for (int o = 16; o; o >>= 1) sum += __shfl_xor_sync(0xffffffffu, sum, o);
            float inv = 1.f / sum;
            for (int s = tid; s < 80; s += 32) sc[s] *= inv;
        }
        __syncthreads();
        for (int k = tid; k < 512; k += 256) {
            float a = 0.f;
            #pragma unroll 8
            for (int s = 0; s < 80; s++) a += sc[s] * enc[((size_t)b * 80 + s) * 512 + k];
            g_ctx[b * 512 + k] = a;
        }
    }
}

// ---------------- Gpre = [emb(tok), ctx] @ W_ih^T + b (432 blocks, occ 2) -------
__global__ void __launch_bounds__(256, 2) gpre_gemm(
    const int* __restrict__ targets, const float* __restrict__ emb,
    const float* __restrict__ Wih, const float* __restrict__ bih,
    const float* __restrict__ bhh) {
    __shared__ float As[2][16 * 128];
    __shared__ float Bs[2][16 * 128];
    __shared__ int tok[128];
    int t = blockIdx.y;
    int nbase = blockIdx.x * 128;
    int tid = threadIdx.x;
    if (tid < 128) tok[tid] = targets[tid * 28 + t];
    __syncthreads();
    int tr = tid >> 4, tc = tid & 15;
    int lr = tid >> 2, lc = (tid & 3) << 2;
    unsigned long long acc[8][4];
    #pragma unroll
    for (int i = 0; i < 8; i++)
        #pragma unroll
        for (int j = 0; j < 4; j++) acc[i][j] = 0ull;

    float4 ra0, ra1, rb0, rb1;
    ra0 = *(const float4*)(emb + (size_t)tok[lr] * 512 + lc);
    ra1 = *(const float4*)(emb + (size_t)tok[lr + 64] * 512 + lc);
    rb0 = *(const float4*)(Wih + (size_t)(nbase + lr) * 1024 + lc);
    rb1 = *(const float4*)(Wih + (size_t)(nbase + lr + 64) * 1024 + lc);
    stT(As[0], lr, lc, ra0); stT(As[0], lr + 64, lc, ra1);
    stT(Bs[0], lr, lc, rb0); stT(Bs[0], lr + 64, lc, rb1);
    __syncthreads();

    int cur = 0;
    for (int kt = 0; kt < 64; kt++) {
        if (kt < 63) {
            int k0 = (kt + 1) * 16;
            if (k0 < 512) {
                ra0 = *(const float4*)(emb + (size_t)tok[lr] * 512 + k0 + lc);
                ra1 = *(const float4*)(emb + (size_t)tok[lr + 64] * 512 + k0 + lc);
            } else {
                ra0 = *(const float4*)(g_ctx + (size_t)lr * 512 + (k0 - 512) + lc);
                ra1 = *(const float4*)(g_ctx + (size_t)(lr + 64) * 512 + (k0 - 512) + lc);
            }
            rb0 = *(const float4*)(Wih + (size_t)(nbase + lr) * 1024 + k0 + lc);
            rb1 = *(const float4*)(Wih + (size_t)(nbase + lr + 64) * 1024 + k0 + lc);
        }
        tile_fma(As[cur], Bs[cur], tr, tc, acc);
        if (kt < 63) {
            stT(As[cur ^ 1], lr, lc, ra0); stT(As[cur ^ 1], lr + 64, lc, ra1);
            stT(Bs[cur ^ 1], lr, lc, rb0); stT(Bs[cur ^ 1], lr + 64, lc, rb1);
        }
        __syncthreads();
        cur ^= 1;
    }
    #pragma unroll
    for (int i = 0; i < 8; i++) {
        int b = (i < 4) ? tr * 4 + i : 64 + tr * 4 + (i - 4);
        float* dst = g_Gpre + ((size_t)t * 128 + b) * 2048;
        #pragma unroll
        for (int j = 0; j < 4; j++) {
            int nc = nbase + ((j >> 1) << 6) + tc * 4 + ((j & 1) << 1);
            float2 v = unpack2(acc[i][j]);
            dst[nc] = v.x + bih[nc] + bhh[nc];
            dst[nc + 1] = v.y + bih[nc + 1] + bhh[nc + 1];
        }
    }
}

// ---------------- persistent LSTM chain — gate-grouped, 1 barrier/step ----------
// block bid owns cols j in {4bid..4bid+3} across all 4 gates (16 W_hh rows, full K)
// smem: SBd (B dup f32x2) 64KB | As (A dbl-buf) 16KB | Sg gates 8.5KB | Cc c 2KB
__device__ __forceinline__ void stA(float* As, int idx, float4 v) {
    int m = idx >> 2, kq = (idx & 3) * 4;
    As[(kq + 0) * 128 + m] = v.x;
    As[(kq + 1) * 128 + m] = v.y;
    As[(kq + 2) * 128 + m] = v.z;
    As[(kq + 3) * 128 + m] = v.w;
}
__global__ void __launch_bounds__(256, 1) lstm_chain(const float* __restrict__ elhs,
                                                     const float* __restrict__ Whh) {
    extern __shared__ float chsm[];
    float2* SBd = (float2*)chsm;          // [k*16 + c], dup pairs (16384 floats)
    float* As  = chsm + 16384;            // [buf*2048 + kk*128 + m] (4096)
    float* Sg  = chsm + 20480;            // [m*17 + c] padded (2176)
    float* Cc  = chsm + 22656;            // [m*4 + u] (512)
    int tid = threadIdx.x, bid = blockIdx.x;
    int jb = bid * 4;
    int rp = tid & 63, cg = tid >> 6;     // row-pair (2rp,2rp+1), col group (gate)

    // load W_hh rows for this block's 16 (gate,u) cols, duplicated
    for (int i = 0; i < 32; i++) {
        int idx = i * 256 + tid;
        int k = idx & 511, c = idx >> 9;
        float w = Whh[(size_t)(512 * (c >> 2) + jb + (c & 3)) * 512 + k];
        SBd[k * 16 + c] = make_float2(w, w);
    }
    Cc[tid] = 0.f;
    Cc[tid + 256] = 0.f;
    unsigned epoch = *(volatile unsigned*)&g_bar_gen;
    __syncthreads();

    for (int t = 0; t < 27; t++) {
        const float* A = (t == 0) ? elhs : (g_H2 + (size_t)(t - 1) * 65536);

        // prologue: chunk 0 -> buf 0
        {
            int idx1 = tid + 256;
            float4 v0 = __ldcg((const float4*)(A + (size_t)(tid >> 2) * 512 + (tid & 3) * 4));
            float4 v1 = __ldcg((const float4*)(A + (size_t)(idx1 >> 2) * 512 + (idx1 & 3) * 4));
            stA(As, tid, v0);
            stA(As, idx1, v1);
        }
        __syncthreads();

        unsigned long long acc[4] = {0ull, 0ull, 0ull, 0ull};
        int cur = 0;
        for (int ci = 0; ci < 32; ci++) {
            float4 v0, v1;
            if (ci < 31) {
                int kb = (ci + 1) * 16;
                int idx1 = tid + 256;
                v0 = __ldcg((const float4*)(A + (size_t)(tid >> 2) * 512 + kb + (tid & 3) * 4));
                v1 = __ldcg((const float4*)(A + (size_t)(idx1 >> 2) * 512 + kb + (idx1 & 3) * 4));
            }
            const float* Ac = As + cur * 2048;
            const float2* Bc = SBd + (size_t)ci * 256;   // 16 k-rows x 16 cols
            #pragma unroll
            for (int kk = 0; kk < 16; kk++) {
                unsigned long long ap = *(const unsigned long long*)(Ac + kk * 128 + 2 * rp);
                ulonglong2 b01 = *(const ulonglong2*)(Bc + kk * 16 + 4 * cg);
                ulonglong2 b23 = *(const ulonglong2*)(Bc + kk * 16 + 4 * cg + 2);
                ffma2(acc[0], ap, b01.x);
                ffma2(acc[1], ap, b01.y);
                ffma2(acc[2], ap, b23.x);
                ffma2(acc[3], ap, b23.y);
            }
            if (ci < 31) {
                stA(As + (cur ^ 1) * 2048, tid, v0);
                stA(As + (cur ^ 1) * 2048, tid + 256, v1);
            }
            __syncthreads();
            cur ^= 1;
        }

        // gates -> Sg (padded stride 17)
        #pragma unroll
        for (int c = 0; c < 4; c++) {
            float2 v = unpack2(acc[c]);
            Sg[(2 * rp) * 17 + cg * 4 + c] = v.x;
            Sg[(2 * rp + 1) * 17 + cg * 4 + c] = v.y;
        }
        __syncthreads();

        // pointwise: 512 outputs (128 m x 4 u), 2 per thread; all local
        #pragma unroll
        for (int e = 0; e < 2; e++) {
            int o = e * 256 + tid;
            int m = o >> 2, u = o & 3;
            const float* Gp = g_Gpre + ((size_t)t * 128 + m) * 2048 + jb + u;
            float gi = Sg[m * 17 + u]      + Gp[0];
            float gf = Sg[m * 17 + 4 + u]  + Gp[512];
            float gg = Sg[m * 17 + 8 + u]  + Gp[1024];
            float go = Sg[m * 17 + 12 + u] + Gp[1536];
            float cprev = Cc[o];
            float si = 1.f / (1.f + expf(-gi));
            float sf = 1.f / (1.f + expf(-gf));
            float so = 1.f / (1.f + expf(-go));
            float c2 = sf * cprev + si * tanhf(gg);
            float h2 = so * tanhf(c2);
            Cc[o] = c2;
            size_t hidx = (size_t)t * 65536 + (size_t)m * 512 + jb + u;
            g_H2[hidx] = h2;
            __nv_bfloat16 hh = __float2bfloat16_rn(h2);
            g_Ahi[hidx] = hh;
            g_Alo[hidx] = __float2bfloat16_rn(h2 - __bfloat162float(hh));
        }
        gsync(++epoch);
    }
}

// ---------------- HMMA logits GEMM (k32 chunks, 3-stage, occ 2) -----------------
// stage (32KB): Ahi@0, Alo@8K, Bhi@16K, Blo@24K; 16-k sub-tiles at +0 / +4096
__global__ void __launch_bounds__(256, 2) hmma_logits(const float* __restrict__ bout,
                                                      float* __restrict__ out) {
    extern __shared__ char lsm[];
    int tid = threadIdx.x;
    int lane = tid & 31, wid = tid >> 5;
    int wm = wid & 1, wn = wid >> 1;
    int ntile = blockIdx.x, mtile = blockIdx.y;
    int mbase = mtile * 128, nbase = ntile * 128;

    const __nv_bfloat16* gAh = g_Ahi + (size_t)mbase * 512;
    const __nv_bfloat16* gAl = g_Alo + (size_t)mbase * 512;
    const __nv_bfloat16* gBh = g_Whi + (size_t)nbase * 512;
    const __nv_bfloat16* gBl = g_Wlo + (size_t)nbase * 512;

    int r = tid & 127, kb = tid >> 7;
    uint32_t dstoff = (uint32_t)(((r >> 3) * 2 + kb) * 128 + (r & 7) * 16);
    size_t srcoff = (size_t)r * 512 + kb * 8;
    uint32_t sbase = smem_u32(lsm);

    uint32_t a_lane = (uint32_t)(((((lane >> 3) & 1) * 2 + (lane >> 4)) * 128) + (lane & 7) * 16);
    uint32_t b_lane = (uint32_t)((((lane >> 3) & 3) * 128) + (lane & 7) * 16);

    float d[4][4][4];
    #pragma unroll
    for (int i = 0; i < 4; i++)
        #pragma unroll
        for (int j = 0; j < 4; j++)
            #pragma unroll
            for (int q = 0; q < 4; q++) d[i][j][q] = 0.f;

    // loader: one k32 chunk -> one stage (8 cp16/thread, one commit group)
    auto load_chunk = [&](int C, int st) {
        uint32_t sb = sbase + (uint32_t)st * 32768u;
        #pragma unroll
        for (int s = 0; s < 2; s++) {
            size_t so = srcoff + (size_t)C * 32 + s * 16;
            uint32_t db = sb + (uint32_t)s * 4096u + dstoff;
            cp16(db,          gAh + so);
            cp16(db + 8192,   gAl + so);
            cp16(db + 16384,  gBh + so);
            cp16(db + 24576,  gBl + so);
        }
        CP_COMMIT();
    };

    load_chunk(0, 0);
    load_chunk(1, 1);

    for (int c = 0; c < 16; c++) {
        CP_WAIT1();
        __syncthreads();
        uint32_t sb = sbase + (uint32_t)(c % 3) * 32768u;

        #pragma unroll
        for (int s = 0; s < 2; s++) {
            uint32_t sb2 = sb + (uint32_t)s * 4096u;
            uint32_t abase = sb2 + a_lane;
            uint32_t bbase = sb2 + 16384u + b_lane;
            uint32_t a[4][4], b[4][2];
            #pragma unroll
            for (int mt = 0; mt < 4; mt++) ldm_x4(a[mt], abase + (uint32_t)((wm * 4 + mt) * 512));
            #pragma unroll
            for (int p = 0; p < 2; p++) {
                uint32_t rr[4];
                ldm_x4(rr, bbase + (uint32_t)((wn * 4 + 2 * p) * 256));
                b[2 * p][0] = rr[0]; b[2 * p][1] = rr[1];
                b[2 * p + 1][0] = rr[2]; b[2 * p + 1][1] = rr[3];
            }
            #pragma unroll
            for (int mt = 0; mt < 4; mt++)
                #pragma unroll
                for (int nt = 0; nt < 4; nt++) mma_bf16(d[mt][nt], a[mt], b[nt]);
            #pragma unroll
            for (int p = 0; p < 2; p++) {
                uint32_t rr[4];
                ldm_x4(rr, bbase + 8192u + (uint32_t)((wn * 4 + 2 * p) * 256));
                b[2 * p][0] = rr[0]; b[2 * p][1] = rr[1];
                b[2 * p + 1][0] = rr[2]; b[2 * p + 1][1] = rr[3];
            }
            #pragma unroll
            for (int mt = 0; mt < 4; mt++)
                #pragma unroll
                for (int nt = 0; nt < 4; nt++) mma_bf16(d[mt][nt], a[mt], b[nt]);
            #pragma unroll
            for (int mt = 0; mt < 4; mt++) ldm_x4(a[mt], abase + 8192u + (uint32_t)((wm * 4 + mt) * 512));
            #pragma unroll
            for (int p = 0; p < 2; p++) {
                uint32_t rr[4];
                ldm_x4(rr, bbase + (uint32_t)((wn * 4 + 2 * p) * 256));
                b[2 * p][0] = rr[0]; b[2 * p][1] = rr[1];
                b[2 * p + 1][0] = rr[2]; b[2 * p + 1][1] = rr[3];
            }
            #pragma unroll
            for (int mt = 0; mt < 4; mt++)
                #pragma unroll
                for (int nt = 0; nt < 4; nt++) mma_bf16(d[mt][nt], a[mt], b[nt]);
        }

        if (c + 2 < 16) load_chunk(c + 2, (c + 2) % 3);
        else CP_COMMIT();
    }

    // epilogue: logits + per-(row,ntile) max
    __syncthreads();
    unsigned* srow = (unsigned*)lsm;
    if (tid < 128) srow[tid] = 0u;
    __syncthreads();

    float rmax[4][2];
    #pragma unroll
    for (int mt = 0; mt < 4; mt++) { rmax[mt][0] = -3.4e38f; rmax[mt][1] = -3.4e38f; }
    #pragma unroll
    for (int nt = 0; nt < 4; nt++) {
        int n = nbase + wn * 32 + nt * 8 + (lane & 3) * 2;
        if (n >= Vv) continue;
        float bx = bout[n], by = bout[n + 1];
        #pragma unroll
        for (int mt = 0; mt < 4; mt++) {
            int m0 = wm * 64 + mt * 16 + (lane >> 2);
            size_t row0 = (size_t)(m0 * 27 + mtile) * Vv;
            size_t row8 = (size_t)((m0 + 8) * 27 + mtile) * Vv;
            float2 v0 = make_float2(d[mt][nt][0] + bx, d[mt][nt][1] + by);
            float2 v1 = make_float2(d[mt][nt][2] + bx, d[mt][nt][3] + by);
            *(float2*)(out + row0 + n) = v0;
            *(float2*)(out + row8 + n) = v1;
            rmax[mt][0] = fmaxf(rmax[mt][0], fmaxf(v0.x, v0.y));
            rmax[mt][1] = fmaxf(rmax[mt][1], fmaxf(v1.x, v1.y));
        }
    }
    #pragma unroll
    for (int mt = 0; mt < 4; mt++) {
        int q = lane >> 2;
        atomicMax(&srow[wm * 64 + mt * 16 + q],     fenc(rmax[mt][0]));
        atomicMax(&srow[wm * 64 + mt * 16 + q + 8], fenc(rmax[mt][1]));
    }
    __syncthreads();
    if (tid < 128)
        g_tilemax[(size_t)(tid * 27 + mtile) * TMSTRIDE + ntile] = fdec(srow[tid]);
}

// ---------------- argmax: tile-max guided scan + exact-fp32 recheck -------------
__global__ void argmax_exact(const float* __restrict__ logits, float* __restrict__ preds,
                             const float* __restrict__ Wout, const float* __restrict__ bout) {
    __shared__ float sv[256];
    __shared__ float hrow[512];
    __shared__ int scand[64];
    __shared__ int tlist[32];
    __shared__ int ncand, ntl;
    __shared__ float bestv;
    __shared__ int besti;
    int rrow = blockIdx.x;
    int tid = threadIdx.x;
    int b = rrow / 27, t = rrow % 27;
    const float* row = logits + (size_t)rrow * Vv;

    float v = (tid < NTILES) ? g_tilemax[(size_t)rrow * TMSTRIDE + tid] : -3.4e38f;
    sv[tid] = v;
    __syncthreads();
    for (int o = 128; o; o >>= 1) {
        if (tid < o) sv[tid] = fmaxf(sv[tid], sv[tid + o]);
        __syncthreads();
    }
    float thr = sv[0] - 1e-3f;

    const float* h = g_H2 + ((size_t)t * 128 + b) * 512;
    hrow[tid] = h[tid];
    hrow[tid + 256] = h[tid + 256];
    if (tid == 0) { ncand = 0; ntl = 0; bestv = -3.4e38f; besti = 0x7fffffff; }
    __syncthreads();

    if (tid < NTILES && v >= thr) {
        int p = atomicAdd(&ntl, 1);
        if (p < 32) tlist[p] = tid;
    }
    __syncthreads();
    int ntiles = ntl < 32 ? ntl : 32;

    for (int ti = tid >> 7; ti < ntiles; ti += 2) {
        int n = tlist[ti] * 128 + (tid & 127);
        if (n < Vv) {
            float lv = row[n];
            if (lv >= thr) {
                int p = atomicAdd(&ncand, 1);
                if (p < 64) scand[p] = n;
            }
        }
    }
    __syncthreads();
    int nc = ncand < 64 ? ncand : 64;

    for (int ci = 0; ci < nc; ci++) {
        int idx = scand[ci];
        const float* wr = Wout + (size_t)idx * 512;
        float p = 0.f;
        for (int k = tid; k < 512; k += 256) p += hrow[k] * wr[k];
        sv[tid] = p;
        __syncthreads();
        for (int o = 128; o; o >>= 1) {
            if (tid < o) sv[tid] += sv[tid + o];
            __syncthreads();
        }
        if (tid == 0) {
            float ev = sv[0] + bout[idx];
            if (ev > bestv || (ev == bestv && idx < besti)) { bestv = ev; besti = idx; }
        }
        __syncthreads();
    }
    if (tid == 0) preds[rrow] = (float)besti;
}

// -------------------------------------------------------------------------------
#define CHAIN_SMEM (23168 * 4)
#define LOGITS_SMEM (3 * 32768)

extern "C" void kernel_launch(void* const* d_in, const int* in_sizes, int n_in,
                              void* d_out, int out_size) {
    const float* elhs    = (const float*)d_in[0];
    const float* enc     = (const float*)d_in[1];
    const int*   targets = (const int*)d_in[2];
    const float* emb     = (const float*)d_in[3];
    const float* W1      = (const float*)d_in[4];
    const float* W2      = (const float*)d_in[6];
    const float* W3      = (const float*)d_in[8];
    const float* W4      = (const float*)d_in[10];
    const float* w_att   = (const float*)d_in[12];
    const float* W_ih    = (const float*)d_in[13];
    const float* W_hh    = (const float*)d_in[14];
    const float* b_ih    = (const float*)d_in[15];
    const float* b_hh    = (const float*)d_in[16];
    const float* W_out   = (const float*)d_in[17];
    const float* b_out   = (const float*)d_in[18];
    float* out = (float*)d_out;

    // idempotent attribute sets (host-side, not stream ops; no allocation)
    cudaFuncSetAttribute(lstm_chain, cudaFuncAttributeMaxDynamicSharedMemorySize, CHAIN_SMEM);
    cudaFuncSetAttribute(hmma_logits, cudaFuncAttributeMaxDynamicSharedMemorySize, LOGITS_SMEM);

    // 1: split W_out -> bf16 hi/lo (pad region zeroed)
    {
        __nv_bfloat16 *whi, *wlo;
        cudaGetSymbolAddress((void**)&whi, g_Whi);
        cudaGetSymbolAddress((void**)&wlo, g_Wlo);
        split_kernel<<<(VPAD * 512) / 1024, 256>>>(W_out, whi, wlo, Vv * 512);
    }

    // 2: fused fold + attention
    fused_prep<<<NBLK, 256>>>(w_att, W4, W3, W2, W1, enc);

    // 3: Gpre (occ-2, 432 blocks)
    gpre_gemm<<<dim3(16, 27), 256>>>(targets, emb, W_ih, b_ih, b_hh);

    // 4: LSTM chain (gate-grouped, 1 barrier/step)  [profiled slot]
    lstm_chain<<<NBLK, 256, CHAIN_SMEM>>>(elhs, W_hh);

    // 5: logits GEMM (occ 2, k32 3-stage)
    hmma_logits<<<dim3(NTILES, 27), 256, LOGITS_SMEM>>>(b_out, out);

    // 6: argmax (tile-max guided)
    long long main_sz = (long long)3456 * Vv;
    if ((long long)out_size > main_sz)
        argmax_exact<<<3456, 256>>>(out, out + main_sz, W_out, b_out);
}

// round 10
// speedup vs baseline: 1.7145x; 1.7145x over previous
#include <cuda_runtime.h>
#include <cuda_fp16.h>
#include <math.h>
#include <stdint.h>

// ----------------------------------------------------------------------------
// DecoderLSTMWithAttention — R10:
//   - logits GEMM: SINGLE-term fp16 HMMA (A fp16, B fp16, fp32 accum).
//     Calibrated from R9's measured failure (bf16 2-term = 0.85*2^-9 = 1.66e-3):
//     fp16 1-term predicted ~sqrt(2)*0.85*2^-12 ~= 2.9e-4 < 1e-3 threshold.
//     Argmax protected by exact-fp32 recheck regardless.
//   - chain: R7 structure (W_hh smem-resident split-K, 395us measured),
//     pointwise emits fp16 A directly
//   - rest as R7 (fused prep, gpre occ-2, tile-max argmax)
// ----------------------------------------------------------------------------

#define Bb 128
#define Hh 512
#define Tt 27
#define Vv 30000
#define NBLK 128
#define VPAD 30208
#define NTILES 235
#define TMSTRIDE 236

// scratch (device globals: no allocations allowed)
__device__ float g_v0[512];
__device__ float g_v1[512];
__device__ float g_q[512];
__device__ float g_ctx[128 * 512];
__device__ float g_Gpre[27u * 128u * 2048u];
__device__ float g_H2[27u * 128u * 512u];
__device__ float g_c[2][128 * 512];
__device__ float g_part[8u * 128u * 2048u];
__device__ unsigned g_bar_cnt;
__device__ unsigned g_bar_gen;
__device__ float g_tilemax[3456u * TMSTRIDE];
__device__ __half g_Ah[3456u * 512u];
__device__ __half g_Wh[(unsigned)VPAD * 512u];

// ---------------- packed fp32x2 helpers ----------------
__device__ __forceinline__ unsigned long long pack2(float x) {
    unsigned long long r;
    asm("mov.b64 %0, {%1, %1};" : "=l"(r) : "f"(x));
    return r;
}
__device__ __forceinline__ void ffma2(unsigned long long& d, unsigned long long a, unsigned long long b) {
    asm("fma.rn.f32x2 %0, %1, %2, %0;" : "+l"(d) : "l"(a), "l"(b));
}
__device__ __forceinline__ float2 unpack2(unsigned long long v) {
    float lo, hi;
    asm("mov.b64 {%0, %1}, %2;" : "=f"(lo), "=f"(hi) : "l"(v));
    return make_float2(lo, hi);
}

// ---------------- ptx helpers ----------------------------------------------------
__device__ __forceinline__ uint32_t smem_u32(const void* p) {
    uint32_t a;
    asm("{ .reg .u64 t; cvta.to.shared.u64 t, %1; cvt.u32.u64 %0, t; }" : "=r"(a) : "l"(p));
    return a;
}
__device__ __forceinline__ void cp16(uint32_t dst, const void* src) {
    asm volatile("cp.async.cg.shared.global [%0], [%1], 16;" :: "r"(dst), "l"(src));
}
#define CP_COMMIT() asm volatile("cp.async.commit_group;" ::: "memory")
#define CP_WAIT1()  asm volatile("cp.async.wait_group 1;" ::: "memory")
__device__ __forceinline__ void ldm_x4(uint32_t* r, uint32_t addr) {
    asm volatile("ldmatrix.sync.aligned.m8n8.x4.shared.b16 {%0,%1,%2,%3}, [%4];"
        : "=r"(r[0]), "=r"(r[1]), "=r"(r[2]), "=r"(r[3]) : "r"(addr));
}
__device__ __forceinline__ void mma_fp16(float* d, const uint32_t* a, const uint32_t* b) {
    asm volatile("mma.sync.aligned.m16n8k16.row.col.f32.f16.f16.f32 "
        "{%0,%1,%2,%3}, {%4,%5,%6,%7}, {%8,%9}, {%0,%1,%2,%3};"
        : "+f"(d[0]), "+f"(d[1]), "+f"(d[2]), "+f"(d[3])
        : "r"(a[0]), "r"(a[1]), "r"(a[2]), "r"(a[3]), "r"(b[0]), "r"(b[1]));
}
__device__ __forceinline__ unsigned fenc(float x) {
    int i = __float_as_int(x);
    return (i >= 0) ? ((unsigned)i | 0x80000000u) : ~(unsigned)i;
}
__device__ __forceinline__ float fdec(unsigned e) {
    int i = (e & 0x80000000u) ? (int)(e & 0x7fffffffu) : ~(int)e;
    return __int_as_float(i);
}

// ---------------- software grid barrier (tight spin, launch-relative) ----------
__device__ __forceinline__ void gsync(unsigned target) {
    __syncthreads();
    if (threadIdx.x == 0) {
        __threadfence();
        unsigned prev = atomicAdd(&g_bar_cnt, 1u);
        if (prev == NBLK - 1) {
            g_bar_cnt = 0;
            __threadfence();
            *(volatile unsigned*)&g_bar_gen = target;
        } else {
            volatile unsigned* vg = (volatile unsigned*)&g_bar_gen;
            while ((int)(*vg - target) < 0) {}
        }
        __threadfence();
    }
    __syncthreads();
}

// ---------------- FFMA2 GEMM micro-kernel ---------------------------------------
__device__ __forceinline__ void tile_fma(const float* As, const float* Bs, int tr, int tc,
                                         unsigned long long acc[8][4]) {
    #pragma unroll
    for (int kk = 0; kk < 16; kk++) {
        float4 a0 = *(const float4*)(As + kk * 128 + tr * 4);
        float4 a1 = *(const float4*)(As + kk * 128 + 64 + tr * 4);
        ulonglong2 b0 = *(const ulonglong2*)(Bs + kk * 128 + tc * 4);
        ulonglong2 b1 = *(const ulonglong2*)(Bs + kk * 128 + 64 + tc * 4);
        unsigned long long pb0 = b0.x, pb1 = b0.y, pb2 = b1.x, pb3 = b1.y;
        float av[8] = {a0.x, a0.y, a0.z, a0.w, a1.x, a1.y, a1.z, a1.w};
        #pragma unroll
        for (int i = 0; i < 8; i++) {
            unsigned long long pa = pack2(av[i]);
            ffma2(acc[i][0], pa, pb0);
            ffma2(acc[i][1], pa, pb1);
            ffma2(acc[i][2], pa, pb2);
            ffma2(acc[i][3], pa, pb3);
        }
    }
}
__device__ __forceinline__ void stT(float* S, int r, int lc, float4 v) {
    float* d = S + r;
    d[(lc + 0) * 128] = v.x;
    d[(lc + 1) * 128] = v.y;
    d[(lc + 2) * 128] = v.z;
    d[(lc + 3) * 128] = v.w;
}

// ---------------- fp32 -> fp16 convert (W_out) -----------------------------------
__global__ void conv_half(const float* __restrict__ src, __half* __restrict__ dst, int n_src) {
    int i0 = (blockIdx.x * 256 + threadIdx.x) * 4;
    #pragma unroll
    for (int u = 0; u < 4; u++) {
        int i = i0 + u;
        float x = (i < n_src) ? src[i] : 0.f;
        dst[i] = __float2half_rn(x);
    }
}

// ---------------- fused prep: matvec fold -> attention (128 blocks) -------------
__global__ void __launch_bounds__(256) fused_prep(
    const float* __restrict__ w_att, const float* __restrict__ W4,
    const float* __restrict__ W3, const float* __restrict__ W2,
    const float* __restrict__ W1, const float* __restrict__ enc) {
    __shared__ float S[1024];
    int tid = threadIdx.x, bid = blockIdx.x;
    unsigned gen0 = *(volatile unsigned*)&g_bar_gen;

    const float* Ws[4] = {W4, W3, W2, W1};
    #pragma unroll 1
    for (int p = 0; p < 4; p++) {
        const float* W = Ws[p];
        int stride = (p == 3) ? 1024 : 512;
        const float* vin = (p == 0) ? w_att : ((p == 2) ? g_v1 : g_v0);
        float* vout = (p == 0) ? g_v0 : ((p == 1) ? g_v1 : ((p == 2) ? g_v0 : g_q));
        int k = bid * 4 + (tid & 3);
        int s = tid >> 2;
        float a = 0.f;
        #pragma unroll
        for (int u = 0; u < 8; u++) {
            int j = s * 8 + u;
            a += __ldcg(vin + j) * W[(size_t)j * stride + k];
        }
        S[tid] = a;
        __syncthreads();
        if (tid < 4) {
            float acc = 0.f;
            for (int s2 = 0; s2 < 64; s2++) acc += S[tid + 4 * s2];
            vout[bid * 4 + tid] = acc;
        }
        gsync(gen0 + 1 + p);
    }

    {
        float* sq = &S[0];
        float* sc = &S[512];
        int b = bid;
        sq[tid] = __ldcg(g_q + tid);
        sq[tid + 256] = __ldcg(g_q + tid + 256);
        __syncthreads();
        int w = tid >> 5, lane = tid & 31;
        for (int s = w; s < 80; s += 8) {
            const float* e = enc + ((size_t)b * 80 + s) * 512;
            float acc = 0.f;
            for (int k = lane; k < 512; k += 32) acc += e[k] * sq[k];
            #pragma unroll
            for (int o = 16; o; o >>= 1) acc += __shfl_xor_sync(0xffffffffu, acc, o);
            if (lane == 0) sc[s] = acc;
        }
        __syncthreads();
        if (tid < 32) {
            float m = -1e30f;
            for (int s = tid; s < 80; s += 32) m = fmaxf(m, sc[s]);
            #pragma unroll
            for (int o = 16; o; o >>= 1) m = fmaxf(m, __shfl_xor_sync(0xffffffffu, m, o));
            float sum = 0.f;
            for (int s = tid; s < 80; s += 32) { float e = expf(sc[s] - m); sc[s] = e; sum += e; }
            #pragma unroll
            for (int o = 16; o; o >>= 1) sum += __shfl_xor_sync(0xffffffffu, sum, o);
            float inv = 1.f / sum;
            for (int s = tid; s < 80; s += 32) sc[s] *= inv;
        }
        __syncthreads();
        for (int k = tid; k < 512; k += 256) {
            float a = 0.f;
            #pragma unroll 8
            for (int s = 0; s < 80; s++) a += sc[s] * enc[((size_t)b * 80 + s) * 512 + k];
            g_ctx[b * 512 + k] = a;
        }
    }
}

// ---------------- Gpre = [emb(tok), ctx] @ W_ih^T + b (432 blocks, occ 2) -------
__global__ void __launch_bounds__(256, 2) gpre_gemm(
    const int* __restrict__ targets, const float* __restrict__ emb,
    const float* __restrict__ Wih, const float* __restrict__ bih,
    const float* __restrict__ bhh) {
    __shared__ float As[2][16 * 128];
    __shared__ float Bs[2][16 * 128];
    __shared__ int tok[128];
    int t = blockIdx.y;
    int nbase = blockIdx.x * 128;
    int tid = threadIdx.x;
    if (tid < 128) tok[tid] = targets[tid * 28 + t];
    __syncthreads();
    int tr = tid >> 4, tc = tid & 15;
    int lr = tid >> 2, lc = (tid & 3) << 2;
    unsigned long long acc[8][4];
    #pragma unroll
    for (int i = 0; i < 8; i++)
        #pragma unroll
        for (int j = 0; j < 4; j++) acc[i][j] = 0ull;

    float4 ra0, ra1, rb0, rb1;
    ra0 = *(const float4*)(emb + (size_t)tok[lr] * 512 + lc);
    ra1 = *(const float4*)(emb + (size_t)tok[lr + 64] * 512 + lc);
    rb0 = *(const float4*)(Wih + (size_t)(nbase + lr) * 1024 + lc);
    rb1 = *(const float4*)(Wih + (size_t)(nbase + lr + 64) * 1024 + lc);
    stT(As[0], lr, lc, ra0); stT(As[0], lr + 64, lc, ra1);
    stT(Bs[0], lr, lc, rb0); stT(Bs[0], lr + 64, lc, rb1);
    __syncthreads();

    int cur = 0;
    for (int kt = 0; kt < 64; kt++) {
        if (kt < 63) {
            int k0 = (kt + 1) * 16;
            if (k0 < 512) {
                ra0 = *(const float4*)(emb + (size_t)tok[lr] * 512 + k0 + lc);
                ra1 = *(const float4*)(emb + (size_t)tok[lr + 64] * 512 + k0 + lc);
            } else {
                ra0 = *(const float4*)(g_ctx + (size_t)lr * 512 + (k0 - 512) + lc);
                ra1 = *(const float4*)(g_ctx + (size_t)(lr + 64) * 512 + (k0 - 512) + lc);
            }
            rb0 = *(const float4*)(Wih + (size_t)(nbase + lr) * 1024 + k0 + lc);
            rb1 = *(const float4*)(Wih + (size_t)(nbase + lr + 64) * 1024 + k0 + lc);
        }
        tile_fma(As[cur], Bs[cur], tr, tc, acc);
        if (kt < 63) {
            stT(As[cur ^ 1], lr, lc, ra0); stT(As[cur ^ 1], lr + 64, lc, ra1);
            stT(Bs[cur ^ 1], lr, lc, rb0); stT(Bs[cur ^ 1], lr + 64, lc, rb1);
        }
        __syncthreads();
        cur ^= 1;
    }
    #pragma unroll
    for (int i = 0; i < 8; i++) {
        int b = (i < 4) ? tr * 4 + i : 64 + tr * 4 + (i - 4);
        float* dst = g_Gpre + ((size_t)t * 128 + b) * 2048;
        #pragma unroll
        for (int j = 0; j < 4; j++) {
            int nc = nbase + ((j >> 1) << 6) + tc * 4 + ((j & 1) << 1);
            float2 v = unpack2(acc[i][j]);
            dst[nc] = v.x + bih[nc] + bhh[nc];
            dst[nc + 1] = v.y + bih[nc + 1] + bhh[nc + 1];
        }
    }
}

// ---------------- persistent LSTM chain: W_hh smem-resident (R7) ----------------
__global__ void __launch_bounds__(256, 1) lstm_chain(const float* __restrict__ elhs,
                                                     const float* __restrict__ Whh) {
    __shared__ float SB[64 * 128];       // resident B: 128 N x 64 K (k-major)
    __shared__ float As[2][16 * 128];    // A double buffer
    int tid = threadIdx.x;
    int nbase = (blockIdx.x & 15) * 128;
    int ks = blockIdx.x >> 4;
    int kbeg = ks * 64;
    int tr = tid >> 4, tc = tid & 15;
    int lr = tid >> 2, lc = (tid & 3) << 2;

    #pragma unroll
    for (int kc = 0; kc < 4; kc++)
        #pragma unroll
        for (int p = 0; p < 2; p++) {
            float4 v = *(const float4*)(Whh + (size_t)(nbase + lr + p * 64) * 512 + kbeg + kc * 16 + lc);
            stT(SB + kc * 16 * 128, lr + p * 64, lc, v);
        }
    unsigned epoch = *(volatile unsigned*)&g_bar_gen;
    __syncthreads();

    for (int t = 0; t < 27; t++) {
        const float* A = (t == 0) ? elhs : (g_H2 + (size_t)(t - 1) * 128 * 512);
        unsigned long long acc[8][4];
        #pragma unroll
        for (int i = 0; i < 8; i++)
            #pragma unroll
            for (int j = 0; j < 4; j++) acc[i][j] = 0ull;

        float4 ra0, ra1;
        ra0 = *(const float4*)(A + (size_t)lr * 512 + kbeg + lc);
        ra1 = *(const float4*)(A + (size_t)(lr + 64) * 512 + kbeg + lc);
        stT(As[0], lr, lc, ra0); stT(As[0], lr + 64, lc, ra1);
        __syncthreads();
        int cur = 0;
        #pragma unroll
        for (int kt = 0; kt < 4; kt++) {
            if (kt < 3) {
                int k0 = kbeg + (kt + 1) * 16;
                ra0 = *(const float4*)(A + (size_t)lr * 512 + k0 + lc);
                ra1 = *(const float4*)(A + (size_t)(lr + 64) * 512 + k0 + lc);
            }
            tile_fma(As[cur], SB + kt * 16 * 128, tr, tc, acc);
            if (kt < 3) {
                stT(As[cur ^ 1], lr, lc, ra0); stT(As[cur ^ 1], lr + 64, lc, ra1);
            }
            __syncthreads();
            cur ^= 1;
        }
        #pragma unroll
        for (int i = 0; i < 8; i++) {
            int b = (i < 4) ? tr * 4 + i : 64 + tr * 4 + (i - 4);
            float* dst = g_part + ((size_t)ks * 128 + b) * 2048;
            #pragma unroll
            for (int j = 0; j < 4; j++) {
                int nc = nbase + ((j >> 1) << 6) + tc * 4 + ((j & 1) << 1);
                float2 v = unpack2(acc[i][j]);
                dst[nc] = v.x;
                dst[nc + 1] = v.y;
            }
        }
        gsync(++epoch);

        #pragma unroll
        for (int e = 0; e < 2; e++) {
            int idx = e * 32768 + blockIdx.x * 256 + tid;
            int b = idx >> 9, j = idx & 511;
            const float* gp = g_Gpre + ((size_t)t * 128 + b) * 2048;
            float gi = gp[j], gf = gp[j + 512], gg = gp[j + 1024], go = gp[j + 1536];
            #pragma unroll
            for (int kk = 0; kk < 8; kk++) {
                const float* pp = g_part + ((size_t)kk * 128 + b) * 2048;
                gi += __ldcg(pp + j);
                gf += __ldcg(pp + j + 512);
                gg += __ldcg(pp + j + 1024);
                go += __ldcg(pp + j + 1536);
            }
            float cprev = (t == 0) ? 0.f : __ldcg(&g_c[(t - 1) & 1][b * 512 + j]);
            float si = 1.f / (1.f + expf(-gi));
            float sf = 1.f / (1.f + expf(-gf));
            float so = 1.f / (1.f + expf(-go));
            float c2 = sf * cprev + si * tanhf(gg);
            float h2 = so * tanhf(c2);
            g_c[t & 1][b * 512 + j] = c2;
            size_t hidx = (size_t)t * 128 * 512 + b * 512 + j;
            g_H2[hidx] = h2;
            g_Ah[hidx] = __float2half_rn(h2);
        }
        gsync(++epoch);
    }
}

// ---------------- HMMA logits GEMM: single-term fp16, 3-stage pipeline ----------
// stage (8KB): A@0, B@4096
__global__ void __launch_bounds__(256, 2) hmma_logits(const float* __restrict__ bout,
                                                      float* __restrict__ out) {
    __shared__ __align__(128) char smem[3][2][4096];
    int tid = threadIdx.x;
    int lane = tid & 31, wid = tid >> 5;
    int wm = wid & 1, wn = wid >> 1;
    int ntile = blockIdx.x, mtile = blockIdx.y;
    int mbase = mtile * 128, nbase = ntile * 128;

    const __half* gA = g_Ah + (size_t)mbase * 512;
    const __half* gB = g_Wh + (size_t)nbase * 512;

    int r = tid & 127, kb = tid >> 7;
    uint32_t dstoff = (uint32_t)(((r >> 3) * 2 + kb) * 128 + (r & 7) * 16);
    size_t srcoff = (size_t)r * 512 + kb * 8;
    uint32_t sst[3] = { smem_u32(&smem[0][0][0]), smem_u32(&smem[1][0][0]), smem_u32(&smem[2][0][0]) };

    uint32_t a_lane = (uint32_t)(((((lane >> 3) & 1) * 2 + (lane >> 4)) * 128) + (lane & 7) * 16);
    uint32_t b_lane = (uint32_t)((((lane >> 3) & 3) * 128) + (lane & 7) * 16);

    float d[4][4][4];
    #pragma unroll
    for (int i = 0; i < 4; i++)
        #pragma unroll
        for (int j = 0; j < 4; j++)
            #pragma unroll
            for (int q = 0; q < 4; q++) d[i][j][q] = 0.f;

    #pragma unroll
    for (int pc = 0; pc < 2; pc++) {
        uint32_t db = sst[pc] + dstoff;
        size_t so = srcoff + (size_t)pc * 16;
        cp16(db,        gA + so);
        cp16(db + 4096, gB + so);
        CP_COMMIT();
    }

    for (int c = 0; c < 32; c++) {
        CP_WAIT1();
        __syncthreads();
        uint32_t sb = sst[c % 3];

        uint32_t a[4][4], b[4][2];
        uint32_t abase = sb + a_lane;
        uint32_t bbase = sb + 4096u + b_lane;
        #pragma unroll
        for (int mt = 0; mt < 4; mt++) ldm_x4(a[mt], abase + (uint32_t)((wm * 4 + mt) * 512));
        #pragma unroll
        for (int p = 0; p < 2; p++) {
            uint32_t rr[4];
            ldm_x4(rr, bbase + (uint32_t)((wn * 4 + 2 * p) * 256));
            b[2 * p][0] = rr[0]; b[2 * p][1] = rr[1];
            b[2 * p + 1][0] = rr[2]; b[2 * p + 1][1] = rr[3];
        }
        #pragma unroll
        for (int mt = 0; mt < 4; mt++)
            #pragma unroll
            for (int nt = 0; nt < 4; nt++) mma_fp16(d[mt][nt], a[mt], b[nt]);

        if (c + 2 < 32) {
            uint32_t db = sst[(c + 2) % 3] + dstoff;
            size_t so = srcoff + (size_t)(c + 2) * 16;
            cp16(db,        gA + so);
            cp16(db + 4096, gB + so);
        }
        CP_COMMIT();
    }

    // epilogue: logits + per-(row,ntile) max
    __syncthreads();
    unsigned* srow = (unsigned*)&smem[0][0][0];
    if (tid < 128) srow[tid] = 0u;
    __syncthreads();

    float rmax[4][2];
    #pragma unroll
    for (int mt = 0; mt < 4; mt++) { rmax[mt][0] = -3.4e38f; rmax[mt][1] = -3.4e38f; }
    #pragma unroll
    for (int nt = 0; nt < 4; nt++) {
        int n = nbase + wn * 32 + nt * 8 + (lane & 3) * 2;
        if (n >= Vv) continue;
        float bx = bout[n], by = bout[n + 1];
        #pragma unroll
        for (int mt = 0; mt < 4; mt++) {
            int m0 = wm * 64 + mt * 16 + (lane >> 2);
            size_t row0 = (size_t)(m0 * 27 + mtile) * Vv;
            size_t row8 = (size_t)((m0 + 8) * 27 + mtile) * Vv;
            float2 v0 = make_float2(d[mt][nt][0] + bx, d[mt][nt][1] + by);
            float2 v1 = make_float2(d[mt][nt][2] + bx, d[mt][nt][3] + by);
            *(float2*)(out + row0 + n) = v0;
            *(float2*)(out + row8 + n) = v1;
            rmax[mt][0] = fmaxf(rmax[mt][0], fmaxf(v0.x, v0.y));
            rmax[mt][1] = fmaxf(rmax[mt][1], fmaxf(v1.x, v1.y));
        }
    }
    #pragma unroll
    for (int mt = 0; mt < 4; mt++) {
        int q = lane >> 2;
        atomicMax(&srow[wm * 64 + mt * 16 + q],     fenc(rmax[mt][0]));
        atomicMax(&srow[wm * 64 + mt * 16 + q + 8], fenc(rmax[mt][1]));
    }
    __syncthreads();
    if (tid < 128)
        g_tilemax[(size_t)(tid * 27 + mtile) * TMSTRIDE + ntile] = fdec(srow[tid]);
}

// ---------------- argmax: tile-max guided scan + exact-fp32 recheck -------------
__global__ void argmax_exact(const float* __restrict__ logits, float* __restrict__ preds,
                             const float* __restrict__ Wout, const float* __restrict__ bout) {
    __shared__ float sv[256];
    __shared__ float hrow[512];
    __shared__ int scand[64];
    __shared__ int tlist[32];
    __shared__ int ncand, ntl;
    __shared__ float bestv;
    __shared__ int besti;
    int rrow = blockIdx.x;
    int tid = threadIdx.x;
    int b = rrow / 27, t = rrow % 27;
    const float* row = logits + (size_t)rrow * Vv;

    float v = (tid < NTILES) ? g_tilemax[(size_t)rrow * TMSTRIDE + tid] : -3.4e38f;
    sv[tid] = v;
    __syncthreads();
    for (int o = 128; o; o >>= 1) {
        if (tid < o) sv[tid] = fmaxf(sv[tid], sv[tid + o]);
        __syncthreads();
    }
    float thr = sv[0] - 1e-3f;

    const float* h = g_H2 + ((size_t)t * 128 + b) * 512;
    hrow[tid] = h[tid];
    hrow[tid + 256] = h[tid + 256];
    if (tid == 0) { ncand = 0; ntl = 0; bestv = -3.4e38f; besti = 0x7fffffff; }
    __syncthreads();

    if (tid < NTILES && v >= thr) {
        int p = atomicAdd(&ntl, 1);
        if (p < 32) tlist[p] = tid;
    }
    __syncthreads();
    int ntiles = ntl < 32 ? ntl : 32;

    for (int ti = tid >> 7; ti < ntiles; ti += 2) {
        int n = tlist[ti] * 128 + (tid & 127);
        if (n < Vv) {
            float lv = row[n];
            if (lv >= thr) {
                int p = atomicAdd(&ncand, 1);
                if (p < 64) scand[p] = n;
            }
        }
    }
    __syncthreads();
    int nc = ncand < 64 ? ncand : 64;

    for (int ci = 0; ci < nc; ci++) {
        int idx = scand[ci];
        const float* wr = Wout + (size_t)idx * 512;
        float p = 0.f;
        for (int k = tid; k < 512; k += 256) p += hrow[k] * wr[k];
        sv[tid] = p;
        __syncthreads();
        for (int o = 128; o; o >>= 1) {
            if (tid < o) sv[tid] += sv[tid + o];
            __syncthreads();
        }
        if (tid == 0) {
            float ev = sv[0] + bout[idx];
            if (ev > bestv || (ev == bestv && idx < besti)) { bestv = ev; besti = idx; }
        }
        __syncthreads();
    }
    if (tid == 0) preds[rrow] = (float)besti;
}

// -------------------------------------------------------------------------------
extern "C" void kernel_launch(void* const* d_in, const int* in_sizes, int n_in,
                              void* d_out, int out_size) {
    const float* elhs    = (const float*)d_in[0];
    const float* enc     = (const float*)d_in[1];
    const int*   targets = (const int*)d_in[2];
    const float* emb     = (const float*)d_in[3];
    const float* W1      = (const float*)d_in[4];
    const float* W2      = (const float*)d_in[6];
    const float* W3      = (const float*)d_in[8];
    const float* W4      = (const float*)d_in[10];
    const float* w_att   = (const float*)d_in[12];
    const float* W_ih    = (const float*)d_in[13];
    const float* W_hh    = (const float*)d_in[14];
    const float* b_ih    = (const float*)d_in[15];
    const float* b_hh    = (const float*)d_in[16];
    const float* W_out   = (const float*)d_in[17];
    const float* b_out   = (const float*)d_in[18];
    float* out = (float*)d_out;

    // 1: convert W_out -> fp16 (pad region zeroed)
    {
        __half* wh;
        cudaGetSymbolAddress((void**)&wh, g_Wh);
        conv_half<<<(VPAD * 512) / 1024, 256>>>(W_out, wh, Vv * 512);
    }

    // 2: fused fold + attention
    fused_prep<<<NBLK, 256>>>(w_att, W4, W3, W2, W1, enc);

    // 3: Gpre (occ-2, 432 blocks)
    gpre_gemm<<<dim3(16, 27), 256>>>(targets, emb, W_ih, b_ih, b_hh);

    // 4: LSTM chain (R7 structure, emits fp16 A)  [profiled slot]
    lstm_chain<<<NBLK, 256>>>(elhs, W_hh);

    // 5: logits GEMM (single-term fp16, occ 2, 3-stage)
    hmma_logits<<<dim3(NTILES, 27), 256>>>(b_out, out);

    // 6: argmax (tile-max guided)
    long long main_sz = (long long)3456 * Vv;
    if ((long long)out_size > main_sz)
        argmax_exact<<<3456, 256>>>(out, out + main_sz, W_out, b_out);
}